// round 9
// baseline (speedup 1.0000x reference)
#include <cuda_runtime.h>
#include <math.h>

#define A_TOTAL 8732
#define N_GT    100
#define B_BATCH 64
#define EPSV    1e-6f
#define BA      (B_BATCH * A_TOTAL)
#define BN      (B_BATCH * N_GT)

// Scratch (no allocations allowed -> __device__ globals)
__device__ unsigned long long g_gt_best[BN];  // per (b,n): packed (iou_bits<<32)|(0xFFFFFFFF-a)
__device__ int    g_forced[BA];               // per (b,a): forced gt index (last n wins) or -1
__device__ float2 g_biu[BA];                  // per (b,a): (best inter, best union) over n
__device__ int    g_bn[BA];                   // per (b,a): first argmax over n
__device__ float4 g_anc_pre[A_TOTAL];         // {1/w, 1/h, log(w+eps), log(h+eps)}
__device__ float4 g_gt_pre[BN];               // {mcx, mcy, log(mw+eps), log(mh+eps)}

// ---------------- prologue: sentinel init + log/rcp precompute ----------------
__global__ void k_pre(const float4* __restrict__ anchors_cxcywh,
                      const float4* __restrict__ gt_boxes) {
    int i = blockIdx.x * blockDim.x + threadIdx.x;
    if (i < A_TOTAL) {
        float4 an = anchors_cxcywh[i];
        g_anc_pre[i] = make_float4(__fdiv_rn(1.0f, an.z), __fdiv_rn(1.0f, an.w),
                                   logf(an.z + EPSV),     logf(an.w + EPSV));
    }
    int j = i - A_TOTAL;
    if (j >= 0 && j < BN) {
        float4 g = gt_boxes[j];                       // xyxy
        float mw = __fsub_rn(g.z, g.x);
        float mh = __fsub_rn(g.w, g.y);
        g_gt_pre[j] = make_float4(0.5f * __fadd_rn(g.x, g.z),
                                  0.5f * __fadd_rn(g.y, g.w),
                                  logf(mw + EPSV), logf(mh + EPSV));
        g_gt_best[j] = 0xFFFFFFFFull;                 // iou=0, a=0 sentinel
    }
}

// ---------------- main IoU / dual-argmax kernel ----------------
__global__ void __launch_bounds__(256) k_iou(
    const float4* __restrict__ gt_boxes,      // (B, N, 4) xyxy
    const float4* __restrict__ anchors_xyxy)  // (A, 4)
{
    __shared__ float4 s_gt[N_GT];
    __shared__ float  s_area[N_GT];
    __shared__ unsigned long long s_best[N_GT];

    const int b   = blockIdx.y;
    const int tid = threadIdx.x;

    if (tid < N_GT) {
        float4 g = gt_boxes[b * N_GT + tid];
        s_gt[tid]   = g;
        s_area[tid] = __fmul_rn(__fsub_rn(g.z, g.x), __fsub_rn(g.w, g.y));
        s_best[tid] = 0xFFFFFFFFull;
    }
    __syncthreads();

    const int a = blockIdx.x * blockDim.x + tid;
    if (a < A_TOTAL) {
        float4 an = anchors_xyxy[a];
        const float Sa = __fmul_rn(__fsub_rn(an.z, an.x), __fsub_rn(an.w, an.y));
        const unsigned int akey = 0xFFFFFFFFu - (unsigned int)a;

        float bi = 0.0f, bu = 1.0f;   // best (inter, union): iou=0 start
        int   bn = 0;

        #pragma unroll 4
        for (int n = 0; n < N_GT; n++) {
            float4 g = s_gt[n];
            float lx = fmaxf(an.x, g.x);
            float ly = fmaxf(an.y, g.y);
            float rx = fminf(an.z, g.z);
            float ry = fminf(an.w, g.w);
            float w = __fsub_rn(rx, lx);
            float h = __fsub_rn(ry, ly);
            if (w > 0.0f && h > 0.0f) {
                float i = __fmul_rn(w, h);
                float u = __fsub_rn(__fadd_rn(Sa, s_area[n]), i);

                // ---- anchor-side argmax: division-free cross-multiply compare.
                // beat <=> rn(i/u) > rn(bi/bu) (reference semantics, first max wins)
                float x = __fmul_rn(i, bu);
                float y = __fmul_rn(bi, u);
                bool beat;
                if      (x > __fmul_rn(y, 1.000001f)) beat = true;
                else if (x < __fmul_rn(y, 0.999999f)) beat = false;
                else    beat = __fdiv_rn(i, u) > __fdiv_rn(bi, bu);  // near-tie exact
                if (beat) { bi = i; bu = u; bn = n; }

                // ---- gt-side max: division-free filter, exact div only on records.
                // hi word of packed key = current best iou bits (monotone).
                float bv = __uint_as_float(
                    reinterpret_cast<const unsigned int*>(&s_best[n])[1]);
                if (i >= __fmul_rn(__fmul_rn(bv, u), 0.999999f)) {
                    float q = __fdiv_rn(i, u);   // bit-exact iou
                    unsigned long long key =
                        ((unsigned long long)__float_as_uint(q) << 32) | akey;
                    if (key > s_best[n]) atomicMax(&s_best[n], key);
                }
            }
        }
        const int o = b * A_TOTAL + a;
        g_biu[o]    = make_float2(bi, bu);
        g_bn[o]     = bn;
        g_forced[o] = -1;
    }
    __syncthreads();
    if (tid < N_GT) {
        unsigned long long v = s_best[tid];
        if (v > 0xFFFFFFFFull)
            atomicMax(&g_gt_best[b * N_GT + tid], v);
    }
}

// ---------------- forced-match scatter (last n wins -> atomicMax) ----------------
__global__ void k_assign() {
    int i = blockIdx.x * blockDim.x + threadIdx.x;   // i = b*N + n
    if (i < BN) {
        int b = i / N_GT;
        int n = i - b * N_GT;
        unsigned int abest = 0xFFFFFFFFu - (unsigned int)(g_gt_best[i] & 0xFFFFFFFFull);
        atomicMax(&g_forced[b * A_TOTAL + (int)abest], n);
    }
}

// ---------------- encode epilogue (MUFU-free) ----------------
__global__ void __launch_bounds__(256) k_encode(
    const int*    __restrict__ gt_labels,       // (B, N)
    const float4* __restrict__ anchors_cxcywh,  // (A, 4)
    float* __restrict__ out)
{
    const int a = blockIdx.x * blockDim.x + threadIdx.x;
    if (a >= A_TOTAL) return;
    const int b = blockIdx.y;
    const int i = b * A_TOTAL + a;

    int  f = g_forced[i];
    bool pos;
    int  idx;
    if (f >= 0) { pos = true; idx = f; }
    else {
        idx = g_bn[i];
        float2 biu = g_biu[i];
        float t = 0.5f * biu.y;                    // exact (exponent shift)
        if      (biu.x > __fmul_rn(t, 1.000001f)) pos = true;
        else if (biu.x < __fmul_rn(t, 0.999999f)) pos = false;
        else    pos = __fdiv_rn(biu.x, biu.y) > 0.5f;   // rn(iou) > 0.5, exact
    }

    float4 gp = g_gt_pre[b * N_GT + idx];           // {mcx, mcy, log mw, log mh}
    float4 an = anchors_cxcywh[a];                  // cx, cy, w, h
    float4 ap = g_anc_pre[a];                       // {1/w, 1/h, log w, log h}

    float ecx = __fmul_rn(__fsub_rn(gp.x, an.x), ap.x);
    float ecy = __fmul_rn(__fsub_rn(gp.y, an.y), ap.y);
    float ew  = __fsub_rn(gp.z, ap.z);
    float eh  = __fsub_rn(gp.w, ap.w);

    int lbl = pos ? gt_labels[b * N_GT + idx] : 0;

    // Output layout: [labels (BA)] [encoded (BA*4)] [pos_mask (BA)], all f32
    out[i] = (float)lbl;
    reinterpret_cast<float4*>(out + BA)[i] = make_float4(ecx, ecy, ew, eh);
    out[5 * BA + i] = pos ? 1.0f : 0.0f;
}

extern "C" void kernel_launch(void* const* d_in, const int* in_sizes, int n_in,
                              void* d_out, int out_size)
{
    const int*    gt_labels      = (const int*)   d_in[0];   // (64,100) int32
    const float4* gt_boxes       = (const float4*)d_in[1];   // (64,100,4) f32
    const float4* anchors_cxcywh = (const float4*)d_in[2];   // (8732,4) f32
    const float4* anchors_xyxy   = (const float4*)d_in[3];   // (8732,4) f32
    float*        out            = (float*)d_out;

    k_pre<<<(A_TOTAL + BN + 255) / 256, 256>>>(anchors_cxcywh, gt_boxes);

    dim3 grid1((A_TOTAL + 255) / 256, B_BATCH);
    k_iou<<<grid1, 256>>>(gt_boxes, anchors_xyxy);

    k_assign<<<(BN + 255) / 256, 256>>>();

    dim3 grid2((A_TOTAL + 255) / 256, B_BATCH);
    k_encode<<<grid2, 256>>>(gt_labels, anchors_cxcywh, out);
}